// round 8
// baseline (speedup 1.0000x reference)
#include <cuda_runtime.h>
#include <cuda_fp16.h>
#include <cstdint>

// Problem constants
#define N_ROWS   32768
#define D_DIM    512
#define C_BOOKS  64
#define K_CODES  16
#define M_OUT    128
#define NODES    15

// ---------------------------------------------------------------------------
// PTX helpers (sm_103 baseline — harness ptxas targets sm_103, no tcgen05)
// ---------------------------------------------------------------------------
__device__ __forceinline__ uint32_t smem_u32(const void* p) {
    uint32_t a;
    asm("{ .reg .u64 t; cvta.to.shared.u64 t, %1; cvt.u32.u64 %0, t; }" : "=r"(a) : "l"(p));
    return a;
}
__device__ __forceinline__ void ldsm4(uint32_t& r0, uint32_t& r1, uint32_t& r2,
                                      uint32_t& r3, uint32_t addr) {
    asm volatile("ldmatrix.sync.aligned.m8n8.x4.shared.b16 {%0,%1,%2,%3}, [%4];"
                 : "=r"(r0), "=r"(r1), "=r"(r2), "=r"(r3) : "r"(addr));
}
__device__ __forceinline__ void mma16816(float* c, uint32_t a0, uint32_t a1,
                                         uint32_t a2, uint32_t a3,
                                         uint32_t b0, uint32_t b1) {
    asm volatile("mma.sync.aligned.m16n8k16.row.col.f32.f16.f16.f32 "
                 "{%0,%1,%2,%3}, {%4,%5,%6,%7}, {%8,%9}, {%0,%1,%2,%3};"
                 : "+f"(c[0]), "+f"(c[1]), "+f"(c[2]), "+f"(c[3])
                 : "r"(a0), "r"(a1), "r"(a2), "r"(a3), "r"(b0), "r"(b1));
}

// ---------------------------------------------------------------------------
// Single fused kernel: per CTA = 128 rows.
//   Phase 1 (encode): 16 subtiles x 8 rows of I, LDG->STS reg-double-buffered;
//                     each thread runs 2 depth-4 trees/subtile; codes -> smem.
//   Phase 2 (MMA):    out[tile] = E @ L^T via mma.sync m16n8k16; A one-hot
//                     synthesized in registers from codes; B staged per
//                     128-k chunk from fp32 L with inline fp16 convert,
//                     double buffered, 1 sync per chunk.
// ---------------------------------------------------------------------------
#define FT        256
#define NTILE     128
#define ROW_PAD   516
#define BROW      272                      // 256B fp16 data + 16B pad per m-row
#define BTILE_B   (128 * BROW)             // 34816
// smem byte offsets
#define SM_CODES  0                        // 128 rows * 32B = 4096
#define SM_TS     4096                     // 960 floats = 3840
#define SM_DS     7936                     // 256 ints = 1024
#define SM_IBUF   8960                     // 8 * 516 * 4 = 16512
#define SM_B      25600                    // 2 * 34816 = 69632
#define SM_TOTAL  (SM_B + 2 * BTILE_B)     // 95232  -> 2 CTAs/SM

__global__ __launch_bounds__(FT, 2)
void fused_kernel(const float* __restrict__ I,
                  const float* __restrict__ T,
                  const int*   __restrict__ dims,
                  const float* __restrict__ L,
                  float* __restrict__ out)
{
    extern __shared__ __align__(16) char smem[];
    const uint32_t sb = smem_u32(smem);
    const int tid = threadIdx.x;
    const int n0  = blockIdx.x * NTILE;

    float* Ts = (float*)(smem + SM_TS);
    int*   ds = (int*)(smem + SM_DS);
    float* Ir = (float*)(smem + SM_IBUF);

    // Thresholds + dims
    if (tid < 240) ((float4*)Ts)[tid] = ((const float4*)T)[tid];
    ds[tid] = dims[tid];

    // ---------------- Phase 1: encode ----------------
    const int erow = tid >> 5;            // 0..7 (row within subtile)
    const int cg   = tid & 31;            // books 2cg, 2cg+1
    uint8_t* cbytes = (uint8_t*)(smem + SM_CODES);
    const float* Isrc = I + (size_t)n0 * D_DIM;

    float4 v[4];
    #pragma unroll
    for (int i = 0; i < 4; i++) v[i] = ((const float4*)Isrc)[tid + FT * i];

    #pragma unroll 1
    for (int s = 0; s < 16; s++) {
        __syncthreads();                  // Ibuf free; (iter 0: Ts/ds visible)
        #pragma unroll
        for (int i = 0; i < 4; i++) {
            int q = tid + FT * i;         // 1024 float4 per subtile
            int r = q >> 7, j = q & 127;
            ((float4*)(Ir + r * ROW_PAD))[j] = v[i];
        }
        float4 vn[4];
        if (s < 15) {
            const float4* p = (const float4*)(Isrc + (size_t)(s + 1) * 8 * D_DIM);
            #pragma unroll
            for (int i = 0; i < 4; i++) vn[i] = p[tid + FT * i];
        }
        __syncthreads();                  // subtile visible

        const float* row = Ir + erow * ROW_PAD;
        uint32_t pk = 0;
        #pragma unroll
        for (int jj = 0; jj < 2; jj++) {
            const int c = cg * 2 + jj;
            const int*   dp = ds + c * 4;
            const float* tp = Ts + c * NODES;
            const float v0 = row[dp[0]];
            const float v1 = row[dp[1]];
            const float v2 = row[dp[2]];
            const float v3 = row[dp[3]];
            int p;
            p = (v0 > tp[0]) ? 1 : 0;
            p = (p << 1) | ((v1 > tp[1 + p]) ? 1 : 0);
            p = (p << 1) | ((v2 > tp[3 + p]) ? 1 : 0);
            p = (p << 1) | ((v3 > tp[7 + p]) ? 1 : 0);
            pk |= (uint32_t)p << (4 * jj);
        }
        cbytes[(s * 8 + erow) * 32 + cg] = (uint8_t)pk;

        if (s < 15) {
            #pragma unroll
            for (int i = 0; i < 4; i++) v[i] = vn[i];
        }
    }

    // ---------------- Phase 2: MMA ----------------
    const int wid  = tid >> 5;
    const int lane = tid & 31;
    const int g    = lane >> 2;
    const int tg   = lane & 3;

    const int t = lane >> 3;
    const uint32_t lane_m   = (uint32_t)(((t >> 1) * 8) + (lane & 7));
    const uint32_t lane_off = lane_m * BROW + (uint32_t)((t & 1) * 16);

    const int rbase = (wid & 3) * 32;     // warp rows within CTA
    const int mwarp = (wid >> 2) * 64;    // warp m within CTA

    // Stage chunk ch (128 m x 128 k) from fp32 L, converting to fp16.
    #define STAGE(ch, buf)                                                       \
        do {                                                                     \
            const uint32_t bdst = sb + SM_B + (buf) * BTILE_B;                   \
            const float* sL = L + (ch) * 128;                                    \
            _Pragma("unroll")                                                    \
            for (int i = 0; i < 16; i++) {                                       \
                int q = tid + FT * i;                                            \
                int m = q >> 5, j = q & 31;                                      \
                float4 vv = *(const float4*)(sL + (size_t)m * 1024 + j * 4);     \
                uint32_t h0, h1;                                                 \
                asm("cvt.rn.f16x2.f32 %0, %1, %2;" : "=r"(h0)                    \
                    : "f"(vv.y), "f"(vv.x));                                     \
                asm("cvt.rn.f16x2.f32 %0, %1, %2;" : "=r"(h1)                    \
                    : "f"(vv.w), "f"(vv.z));                                     \
                asm volatile("st.shared.v2.b32 [%0], {%1,%2};"                   \
                    :: "r"(bdst + (uint32_t)(m * BROW + j * 8)),                 \
                       "r"(h0), "r"(h1) : "memory");                             \
            }                                                                    \
        } while (0)

    __syncthreads();                      // codes complete
    STAGE(0, 0);

    float acc[2][8][4];
    #pragma unroll
    for (int rt = 0; rt < 2; rt++)
        #pragma unroll
        for (int nb = 0; nb < 8; nb++)
            #pragma unroll
            for (int i = 0; i < 4; i++) acc[rt][nb][i] = 0.f;

    const uint32_t* cs = (const uint32_t*)smem;
    __syncthreads();                      // B0 staged

    #pragma unroll 1
    for (int ch = 0; ch < 8; ch++) {
        if (ch < 7) { STAGE(ch + 1, (ch + 1) & 1); }   // overlaps consume

        const uint32_t bbase = sb + SM_B + (ch & 1) * BTILE_B
                             + (uint32_t)mwarp * BROW + lane_off;

        uint32_t wlo[2], whi[2];
        #pragma unroll
        for (int rt = 0; rt < 2; rt++) {
            wlo[rt] = cs[(rbase + 16 * rt + g)     * 8 + ch];
            whi[rt] = cs[(rbase + 16 * rt + g + 8) * 8 + ch];
        }

        #pragma unroll
        for (int kbl = 0; kbl < 8; kbl++) {
            uint32_t b[4][4];
            #pragma unroll
            for (int p = 0; p < 4; p++) {
                ldsm4(b[p][0], b[p][1], b[p][2], b[p][3],
                      bbase + (uint32_t)(kbl * 32) + (uint32_t)(p * 16 * BROW));
            }
            #pragma unroll
            for (int rt = 0; rt < 2; rt++) {
                const uint32_t klo = (wlo[rt] >> (4 * kbl)) & 15u;
                const uint32_t khi = (whi[rt] >> (4 * kbl)) & 15u;
                const uint32_t hlo = 0x3C00u << ((klo & 1u) << 4);
                const uint32_t hhi = 0x3C00u << ((khi & 1u) << 4);
                const uint32_t slo = klo >> 1, shi = khi >> 1;
                const uint32_t A0 = (slo == (uint32_t)tg)     ? hlo : 0u;
                const uint32_t A1 = (shi == (uint32_t)tg)     ? hhi : 0u;
                const uint32_t A2 = (slo == (uint32_t)tg + 4) ? hlo : 0u;
                const uint32_t A3 = (shi == (uint32_t)tg + 4) ? hhi : 0u;
                #pragma unroll
                for (int p = 0; p < 4; p++) {
                    mma16816(acc[rt][2 * p],     A0, A1, A2, A3, b[p][0], b[p][1]);
                    mma16816(acc[rt][2 * p + 1], A0, A1, A2, A3, b[p][2], b[p][3]);
                }
            }
        }
        __syncthreads();                  // staging ch+1 done, consume ch done
    }

    // Epilogue: STG.64 pairs
    #pragma unroll
    for (int rt = 0; rt < 2; rt++) {
        const int rowA = n0 + rbase + 16 * rt + g;
        #pragma unroll
        for (int nb = 0; nb < 8; nb++) {
            float2 lo = make_float2(acc[rt][nb][0], acc[rt][nb][1]);
            float2 hi = make_float2(acc[rt][nb][2], acc[rt][nb][3]);
            *(float2*)(out + (size_t)rowA * M_OUT + mwarp + nb * 8 + tg * 2)       = lo;
            *(float2*)(out + (size_t)(rowA + 8) * M_OUT + mwarp + nb * 8 + tg * 2) = hi;
        }
    }
    #undef STAGE
}

// ---------------------------------------------------------------------------
extern "C" void kernel_launch(void* const* d_in, const int* in_sizes, int n_in,
                              void* d_out, int out_size)
{
    (void)in_sizes; (void)n_in; (void)out_size;
    const float* I    = (const float*)d_in[0];
    const float* T    = (const float*)d_in[1];
    const float* L    = (const float*)d_in[2];
    const int*   dims = (const int*)d_in[5];
    float* out = (float*)d_out;

    cudaFuncSetAttribute(fused_kernel, cudaFuncAttributeMaxDynamicSharedMemorySize,
                         SM_TOTAL);
    fused_kernel<<<N_ROWS / NTILE, FT, SM_TOTAL>>>(I, T, dims, L, out);
}